// round 4
// baseline (speedup 1.0000x reference)
#include <cuda_runtime.h>
#include <math.h>

#define H 512
#define W 512
#define HW (H*W)
#define CH 32
#define CHW (CH*HW)
#define OD2 518            // output dim of pad-4 conv
#define S2 (OD2*OD2)
#define TILE 16
#define ICB 4

// ---------------- scratch (static __device__, no allocation) ----------------
__device__ float g_t1[CHW];          // conv e1 raw output
__device__ float g_t2[CHW];          // conv e2 raw output (x_emb pre-BN)
__device__ float g_gates[4*CHW];     // f,i,c,o raw conv outputs
__device__ float g_r1[CHW];          // conv r1 raw output
__device__ float g_r2[3*S2];         // conv r2 raw output (518x518)
__device__ double g_sum[8*32];       // per-stage per-channel sum
__device__ double g_sq[8*32];        // per-stage per-channel sum of squares
__device__ float g_mean[8*32];
__device__ float g_rs[8*32];

// ---------------- small kernels ----------------
__global__ void zero_stats() {
    int i = threadIdx.x;             // 256 threads cover 8*32
    g_sum[i] = 0.0; g_sq[i] = 0.0;
}

__global__ void finalize_stats(int stage_base, int nch, double invN) {
    int stage = stage_base + blockIdx.x;
    int t = threadIdx.x;
    if (t < nch) {
        int idx = stage*32 + t;
        double m  = g_sum[idx]*invN;
        double var = g_sq[idx]*invN - m*m;
        g_mean[idx] = (float)m;
        g_rs[idx]   = (float)(1.0 / sqrt(var + 1e-5));
    }
}

// ---------------- fused conv3x3 + BN-stat accumulation ----------------
// MODE 0: raw input
// MODE 1: relu(bn(input))   (bn params = bn_mean/bn_rs)
// MODE 2: concat: ch<32 -> in2 raw (prev_h); ch>=32 -> bn(in[ch-32])
template<int CIN, int COUT, int PAD, int MODE>
__global__ void __launch_bounds__(256)
conv_bn(const float* __restrict__ in, const float* __restrict__ in2,
        const float* __restrict__ w0_, const float* __restrict__ w1_,
        const float* __restrict__ w2_, const float* __restrict__ w3_,
        float* __restrict__ out, long outStrideZ,
        const float* __restrict__ bn_mean, const float* __restrict__ bn_rs,
        double* __restrict__ o_sum, double* __restrict__ o_sq)
{
    constexpr int OWID = W + 2*PAD - 2;
    constexpr int OHEI = H + 2*PAD - 2;

    const int z = blockIdx.z;
    const float* wt = (z == 0) ? w0_ : (z == 1) ? w1_ : (z == 2) ? w2_ : w3_;
    out   += (long)z * outStrideZ;
    o_sum += z * COUT;
    o_sq  += z * COUT;

    __shared__ float s_in[ICB][18][18];
    __shared__ float s_w[ICB][COUT][12];
    __shared__ float s_red[8][COUT][2];

    const int tid = threadIdx.x;
    const int px = tid & 15, py = tid >> 4;
    const int ox = blockIdx.x*TILE + px;
    const int oy = blockIdx.y*TILE + py;
    const bool valid = (ox < OWID) && (oy < OHEI);

    float acc[COUT];
#pragma unroll
    for (int i = 0; i < COUT; i++) acc[i] = 0.f;

    const int gx0 = blockIdx.x*TILE - PAD;
    const int gy0 = blockIdx.y*TILE - PAD;

    for (int ic0 = 0; ic0 < CIN; ic0 += ICB) {
        __syncthreads();
        // load input tile (with fused BN/ReLU/concat transform)
        for (int e = tid; e < ICB*18*18; e += 256) {
            int ic = e / 324; int r = e - ic*324;
            int ly = r / 18, lx = r - ly*18;
            int gy = gy0 + ly, gx = gx0 + lx;
            float v = 0.f;
            if ((unsigned)gy < (unsigned)H && (unsigned)gx < (unsigned)W) {
                int c = ic0 + ic;
                if (MODE == 0) {
                    v = in[(long)c*HW + gy*W + gx];
                } else if (MODE == 1) {
                    float t = in[(long)c*HW + gy*W + gx];
                    t = (t - bn_mean[c]) * bn_rs[c];
                    v = t > 0.f ? t : 0.f;
                } else { // MODE 2
                    if (c < 32) {
                        v = in2[(long)c*HW + gy*W + gx];
                    } else {
                        float t = in[(long)(c-32)*HW + gy*W + gx];
                        v = (t - bn_mean[c-32]) * bn_rs[c-32];
                    }
                }
            }
            s_in[ic][ly][lx] = v;
        }
        // load weights, padded to 12 floats per (ic,oc) row for LDS.128
        for (int e = tid; e < ICB*COUT*12; e += 256) {
            int ic = e / (COUT*12); int r = e - ic*(COUT*12);
            int oc = r / 12, k = r - oc*12;
            s_w[ic][oc][k] = (k < 9) ? wt[((long)oc*CIN + ic0 + ic)*9 + k] : 0.f;
        }
        __syncthreads();

#pragma unroll
        for (int i = 0; i < ICB; i++) {
            float i00 = s_in[i][py+0][px+0], i01 = s_in[i][py+0][px+1], i02 = s_in[i][py+0][px+2];
            float i10 = s_in[i][py+1][px+0], i11 = s_in[i][py+1][px+1], i12 = s_in[i][py+1][px+2];
            float i20 = s_in[i][py+2][px+0], i21 = s_in[i][py+2][px+1], i22 = s_in[i][py+2][px+2];
#pragma unroll
            for (int oc = 0; oc < COUT; oc++) {
                const float4* wp = (const float4*)&s_w[i][oc][0];
                float4 a = wp[0], b = wp[1], c4 = wp[2];
                acc[oc] += i00*a.x + i01*a.y + i02*a.z
                         + i10*a.w + i11*b.x + i12*b.y
                         + i20*b.z + i21*b.w + i22*c4.x;
            }
        }
    }

    // write outputs + accumulate BN stats
    const int lane = tid & 31, wid = tid >> 5;
#pragma unroll
    for (int oc = 0; oc < COUT; oc++) {
        float v = valid ? acc[oc] : 0.f;
        if (valid) out[(long)oc*OHEI*OWID + (long)oy*OWID + ox] = v;
        float s = v, q = v*v;
#pragma unroll
        for (int o2 = 16; o2 > 0; o2 >>= 1) {
            s += __shfl_xor_sync(0xffffffffu, s, o2);
            q += __shfl_xor_sync(0xffffffffu, q, o2);
        }
        if (lane == 0) { s_red[wid][oc][0] = s; s_red[wid][oc][1] = q; }
    }
    __syncthreads();
    if (tid < COUT) {
        double s = 0.0, q = 0.0;
#pragma unroll
        for (int wdx = 0; wdx < 8; wdx++) { s += (double)s_red[wdx][tid][0]; q += (double)s_red[wdx][tid][1]; }
        atomicAdd(&o_sum[tid], s);
        atomicAdd(&o_sq[tid], q);
    }
}

// ---------------- LSTM elementwise ----------------
__device__ __forceinline__ float sigmoidf(float x) { return 1.f / (1.f + expf(-x)); }

__global__ void lstm_elem(const float* __restrict__ prev_c, float* __restrict__ out)
{
    long i = (long)blockIdx.x * blockDim.x + threadIdx.x;
    if (i >= CHW) return;
    int c = (int)(i / HW);
    float f  = sigmoidf((g_gates[i]          - g_mean[64  + c]) * g_rs[64  + c]);
    float it = sigmoidf((g_gates[CHW + i]    - g_mean[96  + c]) * g_rs[96  + c]);
    float ct = tanhf(   (g_gates[2L*CHW + i] - g_mean[128 + c]) * g_rs[128 + c]);
    float ot = sigmoidf((g_gates[3L*CHW + i] - g_mean[160 + c]) * g_rs[160 + c]);
    float nc = prev_c[i] * f + it * ct;
    float nh = tanhf(nc) * ot;
    out[i] = nc;
    out[CHW + i] = nh;
}

// ---------------- gather (K=1 -> single pixel at (hx+3, hy+3)) ----------------
__global__ void gather_k(const int* __restrict__ coords,
                         const float* __restrict__ w_oil, const float* __restrict__ b_oil,
                         const float* __restrict__ w_wat, const float* __restrict__ b_wat,
                         const float* __restrict__ w_gas, const float* __restrict__ b_gas,
                         float* __restrict__ out)
{
    int i = threadIdx.x;
    if (i >= 256) return;
    int hx = coords[2*i], hy = coords[2*i+1];
    int row = hx + 3, col = hy + 3;
    float wv[3] = { w_oil[0], w_wat[0], w_gas[0] };
    float bv[3] = { b_oil[0], b_wat[0], b_gas[0] };
#pragma unroll
    for (int ch = 0; ch < 3; ch++) {
        float v = (g_r2[(long)ch*S2 + (long)row*OD2 + col] - g_mean[224 + ch]) * g_rs[224 + ch];
        out[2L*CHW + (long)i*3 + ch] = v * wv[ch] + bv[ch];
    }
}

// ---------------- launch ----------------
extern "C" void kernel_launch(void* const* d_in, const int* in_sizes, int n_in,
                              void* d_out, int out_size)
{
    const float* x      = (const float*)d_in[0];
    const float* prev_c = (const float*)d_in[1];
    const float* prev_h = (const float*)d_in[2];
    const int*   holes  = (const int*)  d_in[3];
    const float* w_e1   = (const float*)d_in[4];
    const float* w_e2   = (const float*)d_in[5];
    const float* w_f    = (const float*)d_in[6];
    const float* w_i    = (const float*)d_in[7];
    const float* w_c    = (const float*)d_in[8];
    const float* w_o    = (const float*)d_in[9];
    const float* w_r1   = (const float*)d_in[10];
    const float* w_r2   = (const float*)d_in[11];
    const float* w_oil  = (const float*)d_in[12];
    const float* b_oil  = (const float*)d_in[13];
    const float* w_wat  = (const float*)d_in[14];
    const float* b_wat  = (const float*)d_in[15];
    const float* w_gas  = (const float*)d_in[16];
    const float* b_gas  = (const float*)d_in[17];
    float* out = (float*)d_out;

    float *t1, *t2, *gates, *r1, *r2, *mean, *rs;
    double *sum, *sq;
    cudaGetSymbolAddress((void**)&t1,    g_t1);
    cudaGetSymbolAddress((void**)&t2,    g_t2);
    cudaGetSymbolAddress((void**)&gates, g_gates);
    cudaGetSymbolAddress((void**)&r1,    g_r1);
    cudaGetSymbolAddress((void**)&r2,    g_r2);
    cudaGetSymbolAddress((void**)&sum,   g_sum);
    cudaGetSymbolAddress((void**)&sq,    g_sq);
    cudaGetSymbolAddress((void**)&mean,  g_mean);
    cudaGetSymbolAddress((void**)&rs,    g_rs);

    const double invHW = 1.0 / (double)HW;
    const double invS2 = 1.0 / (double)S2;

    dim3 blk(256);
    dim3 g32(32, 32, 1);
    dim3 g4 (32, 32, 4);
    dim3 g33(33, 33, 1);

    zero_stats<<<1, 256>>>();

    // e1: x (4ch) -> t1, stats stage 0
    conv_bn<4, 32, 1, 0><<<g32, blk>>>(x, nullptr, w_e1, w_e1, w_e1, w_e1,
                                       t1, 0, nullptr, nullptr, sum + 0, sq + 0);
    finalize_stats<<<1, 32>>>(0, 32, invHW);

    // e2: relu(bn(t1)) -> t2, stats stage 1
    conv_bn<32, 32, 1, 1><<<g32, blk>>>(t1, nullptr, w_e2, w_e2, w_e2, w_e2,
                                        t2, 0, mean + 0, rs + 0, sum + 32, sq + 32);
    finalize_stats<<<1, 32>>>(1, 32, invHW);

    // gates: concat(prev_h, bn(t2)) -> 4 convs in one launch, stats stages 2..5
    conv_bn<64, 32, 1, 2><<<g4, blk>>>(t2, prev_h, w_f, w_i, w_c, w_o,
                                       gates, (long)CHW, mean + 32, rs + 32, sum + 64, sq + 64);
    finalize_stats<<<4, 32>>>(2, 32, invHW);

    // LSTM pointwise -> next_c, next_h written directly into d_out
    lstm_elem<<<(CHW + 255) / 256, 256>>>(prev_c, out);

    // r1: next_h (raw) -> r1, stats stage 6
    conv_bn<32, 32, 1, 0><<<g32, blk>>>(out + CHW, nullptr, w_r1, w_r1, w_r1, w_r1,
                                        r1, 0, nullptr, nullptr, sum + 192, sq + 192);
    finalize_stats<<<1, 32>>>(6, 32, invHW);

    // r2: relu(bn(r1)) -> r2 (3ch, 518x518, pad 4), stats stage 7
    conv_bn<32, 3, 4, 1><<<g33, blk>>>(r1, nullptr, w_r2, w_r2, w_r2, w_r2,
                                       r2, 0, mean + 192, rs + 192, sum + 224, sq + 224);
    finalize_stats<<<1, 32>>>(7, 3, invS2);

    // gather + tiny matmul (K=1 scalar) -> res
    gather_k<<<1, 256>>>(holes, w_oil, b_oil, w_wat, b_wat, w_gas, b_gas, out);
}

// round 6
// speedup vs baseline: 1.3315x; 1.3315x over previous
#include <cuda_runtime.h>
#include <math.h>

#define H 512
#define W 512
#define HW (H*W)
#define CH 32
#define CHW (CH*HW)
#define OD2 518            // output dim of pad-4 conv
#define S2 (OD2*OD2)
#define TILE 16
#define ICB 4

// ---------------- scratch (static __device__, no allocation) ----------------
__device__ float g_t1[CHW];          // conv e1 raw output
__device__ float g_t2[CHW];          // conv e2 raw output (x_emb pre-BN)
__device__ float g_gates[4*CHW];     // f,i,c,o raw conv outputs
__device__ float g_r1[CHW];          // conv r1 raw output
__device__ float g_r2[3*S2];         // conv r2 raw output (518x518)
__device__ double g_sum[8*32];       // per-stage per-channel sum
__device__ double g_sq[8*32];        // per-stage per-channel sum of squares
__device__ float g_mean[8*32];
__device__ float g_rs[8*32];

// ---------------- f32x2 packed-math helpers ----------------
__device__ __forceinline__ unsigned long long dup2(float v) {
    unsigned long long d;
    asm("mov.b64 %0, {%1, %1};" : "=l"(d) : "f"(v));
    return d;
}
__device__ __forceinline__ void fma2(unsigned long long& d,
                                     unsigned long long a, unsigned long long b) {
    asm("fma.rn.f32x2 %0, %1, %2, %0;" : "+l"(d) : "l"(a), "l"(b));
}
__device__ __forceinline__ float2 unpack2(unsigned long long d) {
    float2 f;
    asm("mov.b64 {%0, %1}, %2;" : "=f"(f.x), "=f"(f.y) : "l"(d));
    return f;
}

// ---------------- small kernels ----------------
__global__ void zero_stats() {
    int i = threadIdx.x;             // 256 threads cover 8*32
    g_sum[i] = 0.0; g_sq[i] = 0.0;
}

__global__ void finalize_stats(int stage_base, int nch, double invN) {
    int stage = stage_base + blockIdx.x;
    int t = threadIdx.x;
    if (t < nch) {
        int idx = stage*32 + t;
        double m  = g_sum[idx]*invN;
        double var = g_sq[idx]*invN - m*m;
        g_mean[idx] = (float)m;
        g_rs[idx]   = (float)(1.0 / sqrt(var + 1e-5));
    }
}

// ---------------- FFMA2 conv3x3 (COUT=32 total, 16 per block) ----------------
// Tile: 64 wide x 16 tall; thread = 4 px (x) x 16 oc (packed as 8 oc-pairs).
// blockIdx.z = gate*2 + oc_half. Only for full 512x512, PAD=1 convs.
// MODE 0: raw input; MODE 1: relu(bn(in)); MODE 2: concat(in2 raw | bn(in))
template<int CIN, int MODE>
__global__ void __launch_bounds__(256, 2)
conv2(const float* __restrict__ in, const float* __restrict__ in2,
      const float* __restrict__ w0_, const float* __restrict__ w1_,
      const float* __restrict__ w2_, const float* __restrict__ w3_,
      float* __restrict__ out, long outStrideZ,
      const float* __restrict__ bn_mean, const float* __restrict__ bn_rs,
      double* __restrict__ o_sum, double* __restrict__ o_sq)
{
    const int z    = blockIdx.z;
    const int gate = z >> 1;
    const int ocbase = (z & 1) * 16;
    const float* wt = (gate == 0) ? w0_ : (gate == 1) ? w1_ : (gate == 2) ? w2_ : w3_;
    out   += (long)gate * outStrideZ;
    o_sum += gate*32 + ocbase;
    o_sq  += gate*32 + ocbase;

    __shared__ float s_in[ICB][18][68];   // 66 used cols, padded
    __shared__ float s_w[ICB][9][16];     // oc-contiguous for LDS.128 pairs
    __shared__ float s_red[8][16][2];

    const int tid = threadIdx.x;
    const int tx = tid & 15, ty = tid >> 4;
    const int x0 = blockIdx.x*64 + tx*4;
    const int oy = blockIdx.y*16 + ty;
    const int gx0 = blockIdx.x*64 - 1;
    const int gy0 = blockIdx.y*16 - 1;

    unsigned long long acc[4][8];
#pragma unroll
    for (int p = 0; p < 4; p++)
#pragma unroll
        for (int q = 0; q < 8; q++) acc[p][q] = 0ULL;

    for (int ic0 = 0; ic0 < CIN; ic0 += ICB) {
        __syncthreads();
        // ---- input tile: ICB x 18 x 66 with fused transform ----
        for (int e = tid; e < ICB*18*66; e += 256) {
            int ic = e / (18*66);
            int r  = e - ic*(18*66);
            int ly = r / 66, lx = r - ly*66;
            int gy = gy0 + ly, gx = gx0 + lx;
            float v = 0.f;
            if ((unsigned)gy < (unsigned)H && (unsigned)gx < (unsigned)W) {
                int c = ic0 + ic;
                if (MODE == 0) {
                    v = in[(long)c*HW + gy*W + gx];
                } else if (MODE == 1) {
                    float t = in[(long)c*HW + gy*W + gx];
                    t = (t - bn_mean[c]) * bn_rs[c];
                    v = t > 0.f ? t : 0.f;
                } else {
                    if (c < 32) {
                        v = in2[(long)c*HW + gy*W + gx];
                    } else {
                        float t = in[(long)(c-32)*HW + gy*W + gx];
                        v = (t - bn_mean[c-32]) * bn_rs[c-32];
                    }
                }
            }
            s_in[ic][ly][lx] = v;
        }
        // ---- weights: ICB x 9 x 16 (this block's oc half) ----
        for (int e = tid; e < ICB*9*16; e += 256) {
            int ic = e / 144;
            int r  = e - ic*144;
            int k  = r >> 4, oco = r & 15;
            s_w[ic][k][oco] = wt[((long)(ocbase + oco)*CIN + ic0 + ic)*9 + k];
        }
        __syncthreads();

#pragma unroll
        for (int i = 0; i < ICB; i++) {
#pragma unroll
            for (int r = 0; r < 3; r++) {
                // 6 consecutive input floats: float4 + float2 (conflict-free)
                float4 va = *(const float4*)&s_in[i][ty + r][tx*4];
                float2 vb = *(const float2*)&s_in[i][ty + r][tx*4 + 4];
                unsigned long long d0 = dup2(va.x), d1 = dup2(va.y);
                unsigned long long d2 = dup2(va.z), d3 = dup2(va.w);
                unsigned long long d4 = dup2(vb.x), d5 = dup2(vb.y);
                unsigned long long d[6] = { d0, d1, d2, d3, d4, d5 };
#pragma unroll
                for (int c = 0; c < 3; c++) {
                    const ulonglong2* wr = (const ulonglong2*)&s_w[i][r*3 + c][0];
                    ulonglong2 wa = wr[0], wb = wr[1], wc = wr[2], wd = wr[3];
                    unsigned long long wv[8] = { wa.x, wa.y, wb.x, wb.y,
                                                 wc.x, wc.y, wd.x, wd.y };
#pragma unroll
                    for (int p = 0; p < 4; p++) {
#pragma unroll
                        for (int q = 0; q < 8; q++)
                            fma2(acc[p][q], d[c + p], wv[q]);
                    }
                }
            }
        }
    }

    // ---- output (float4 stores) + BN stats ----
    const int lane = tid & 31, wid = tid >> 5;
    const long obase = (long)oy*W + x0;
#pragma unroll
    for (int q = 0; q < 8; q++) {
        float2 v0 = unpack2(acc[0][q]), v1 = unpack2(acc[1][q]);
        float2 v2 = unpack2(acc[2][q]), v3 = unpack2(acc[3][q]);
        float4 lo = make_float4(v0.x, v1.x, v2.x, v3.x);
        float4 hi = make_float4(v0.y, v1.y, v2.y, v3.y);
        *(float4*)(out + (long)(ocbase + 2*q    )*HW + obase) = lo;
        *(float4*)(out + (long)(ocbase + 2*q + 1)*HW + obase) = hi;

        float sl = lo.x + lo.y + lo.z + lo.w;
        float ql = lo.x*lo.x + lo.y*lo.y + lo.z*lo.z + lo.w*lo.w;
        float sh = hi.x + hi.y + hi.z + hi.w;
        float qh = hi.x*hi.x + hi.y*hi.y + hi.z*hi.z + hi.w*hi.w;
#pragma unroll
        for (int o2 = 16; o2 > 0; o2 >>= 1) {
            sl += __shfl_xor_sync(0xffffffffu, sl, o2);
            ql += __shfl_xor_sync(0xffffffffu, ql, o2);
            sh += __shfl_xor_sync(0xffffffffu, sh, o2);
            qh += __shfl_xor_sync(0xffffffffu, qh, o2);
        }
        if (lane == 0) {
            s_red[wid][2*q    ][0] = sl; s_red[wid][2*q    ][1] = ql;
            s_red[wid][2*q + 1][0] = sh; s_red[wid][2*q + 1][1] = qh;
        }
    }
    __syncthreads();
    if (tid < 16) {
        double s = 0.0, qq = 0.0;
#pragma unroll
        for (int wdx = 0; wdx < 8; wdx++) {
            s  += (double)s_red[wdx][tid][0];
            qq += (double)s_red[wdx][tid][1];
        }
        atomicAdd(&o_sum[tid], s);
        atomicAdd(&o_sq[tid], qq);
    }
}

// ---------------- legacy conv (kept for e1 (CIN=4) and r2 (COUT=3, 518-wide)) --
template<int CIN, int COUT, int PAD, int MODE>
__global__ void __launch_bounds__(256)
conv_bn(const float* __restrict__ in, const float* __restrict__ in2,
        const float* __restrict__ w0_, const float* __restrict__ w1_,
        const float* __restrict__ w2_, const float* __restrict__ w3_,
        float* __restrict__ out, long outStrideZ,
        const float* __restrict__ bn_mean, const float* __restrict__ bn_rs,
        double* __restrict__ o_sum, double* __restrict__ o_sq)
{
    constexpr int OWID = W + 2*PAD - 2;
    constexpr int OHEI = H + 2*PAD - 2;

    const int z = blockIdx.z;
    const float* wt = (z == 0) ? w0_ : (z == 1) ? w1_ : (z == 2) ? w2_ : w3_;
    out   += (long)z * outStrideZ;
    o_sum += z * COUT;
    o_sq  += z * COUT;

    __shared__ float s_in[ICB][18][18];
    __shared__ float s_w[ICB][COUT][12];
    __shared__ float s_red[8][COUT][2];

    const int tid = threadIdx.x;
    const int px = tid & 15, py = tid >> 4;
    const int ox = blockIdx.x*TILE + px;
    const int oy = blockIdx.y*TILE + py;
    const bool valid = (ox < OWID) && (oy < OHEI);

    float acc[COUT];
#pragma unroll
    for (int i = 0; i < COUT; i++) acc[i] = 0.f;

    const int gx0 = blockIdx.x*TILE - PAD;
    const int gy0 = blockIdx.y*TILE - PAD;

    for (int ic0 = 0; ic0 < CIN; ic0 += ICB) {
        __syncthreads();
        for (int e = tid; e < ICB*18*18; e += 256) {
            int ic = e / 324; int r = e - ic*324;
            int ly = r / 18, lx = r - ly*18;
            int gy = gy0 + ly, gx = gx0 + lx;
            float v = 0.f;
            if ((unsigned)gy < (unsigned)H && (unsigned)gx < (unsigned)W) {
                int c = ic0 + ic;
                if (MODE == 0) {
                    v = in[(long)c*HW + gy*W + gx];
                } else if (MODE == 1) {
                    float t = in[(long)c*HW + gy*W + gx];
                    t = (t - bn_mean[c]) * bn_rs[c];
                    v = t > 0.f ? t : 0.f;
                } else {
                    if (c < 32) {
                        v = in2[(long)c*HW + gy*W + gx];
                    } else {
                        float t = in[(long)(c-32)*HW + gy*W + gx];
                        v = (t - bn_mean[c-32]) * bn_rs[c-32];
                    }
                }
            }
            s_in[ic][ly][lx] = v;
        }
        for (int e = tid; e < ICB*COUT*12; e += 256) {
            int ic = e / (COUT*12); int r = e - ic*(COUT*12);
            int oc = r / 12, k = r - oc*12;
            s_w[ic][oc][k] = (k < 9) ? wt[((long)oc*CIN + ic0 + ic)*9 + k] : 0.f;
        }
        __syncthreads();

#pragma unroll
        for (int i = 0; i < ICB; i++) {
            float i00 = s_in[i][py+0][px+0], i01 = s_in[i][py+0][px+1], i02 = s_in[i][py+0][px+2];
            float i10 = s_in[i][py+1][px+0], i11 = s_in[i][py+1][px+1], i12 = s_in[i][py+1][px+2];
            float i20 = s_in[i][py+2][px+0], i21 = s_in[i][py+2][px+1], i22 = s_in[i][py+2][px+2];
#pragma unroll
            for (int oc = 0; oc < COUT; oc++) {
                const float4* wp = (const float4*)&s_w[i][oc][0];
                float4 a = wp[0], b = wp[1], c4 = wp[2];
                acc[oc] += i00*a.x + i01*a.y + i02*a.z
                         + i10*a.w + i11*b.x + i12*b.y
                         + i20*b.z + i21*b.w + i22*c4.x;
            }
        }
    }

    const int lane = tid & 31, wid = tid >> 5;
#pragma unroll
    for (int oc = 0; oc < COUT; oc++) {
        float v = valid ? acc[oc] : 0.f;
        if (valid) out[(long)oc*OHEI*OWID + (long)oy*OWID + ox] = v;
        float s = v, q = v*v;
#pragma unroll
        for (int o2 = 16; o2 > 0; o2 >>= 1) {
            s += __shfl_xor_sync(0xffffffffu, s, o2);
            q += __shfl_xor_sync(0xffffffffu, q, o2);
        }
        if (lane == 0) { s_red[wid][oc][0] = s; s_red[wid][oc][1] = q; }
    }
    __syncthreads();
    if (tid < COUT) {
        double s = 0.0, q = 0.0;
#pragma unroll
        for (int wdx = 0; wdx < 8; wdx++) { s += (double)s_red[wdx][tid][0]; q += (double)s_red[wdx][tid][1]; }
        atomicAdd(&o_sum[tid], s);
        atomicAdd(&o_sq[tid], q);
    }
}

// ---------------- LSTM elementwise ----------------
__device__ __forceinline__ float sigmoidf(float x) { return 1.f / (1.f + expf(-x)); }

__global__ void lstm_elem(const float* __restrict__ prev_c, float* __restrict__ out)
{
    long i = (long)blockIdx.x * blockDim.x + threadIdx.x;
    if (i >= CHW) return;
    int c = (int)(i / HW);
    float f  = sigmoidf((g_gates[i]          - g_mean[64  + c]) * g_rs[64  + c]);
    float it = sigmoidf((g_gates[CHW + i]    - g_mean[96  + c]) * g_rs[96  + c]);
    float ct = tanhf(   (g_gates[2L*CHW + i] - g_mean[128 + c]) * g_rs[128 + c]);
    float ot = sigmoidf((g_gates[3L*CHW + i] - g_mean[160 + c]) * g_rs[160 + c]);
    float nc = prev_c[i] * f + it * ct;
    float nh = tanhf(nc) * ot;
    out[i] = nc;
    out[CHW + i] = nh;
}

// ---------------- gather (K=1 -> single pixel at (hx+3, hy+3)) ----------------
__global__ void gather_k(const int* __restrict__ coords,
                         const float* __restrict__ w_oil, const float* __restrict__ b_oil,
                         const float* __restrict__ w_wat, const float* __restrict__ b_wat,
                         const float* __restrict__ w_gas, const float* __restrict__ b_gas,
                         float* __restrict__ out)
{
    int i = threadIdx.x;
    if (i >= 256) return;
    int hx = coords[2*i], hy = coords[2*i+1];
    int row = hx + 3, col = hy + 3;
    float wv[3] = { w_oil[0], w_wat[0], w_gas[0] };
    float bv[3] = { b_oil[0], b_wat[0], b_gas[0] };
#pragma unroll
    for (int ch = 0; ch < 3; ch++) {
        float v = (g_r2[(long)ch*S2 + (long)row*OD2 + col] - g_mean[224 + ch]) * g_rs[224 + ch];
        out[2L*CHW + (long)i*3 + ch] = v * wv[ch] + bv[ch];
    }
}

// ---------------- launch ----------------
extern "C" void kernel_launch(void* const* d_in, const int* in_sizes, int n_in,
                              void* d_out, int out_size)
{
    const float* x      = (const float*)d_in[0];
    const float* prev_c = (const float*)d_in[1];
    const float* prev_h = (const float*)d_in[2];
    const int*   holes  = (const int*)  d_in[3];
    const float* w_e1   = (const float*)d_in[4];
    const float* w_e2   = (const float*)d_in[5];
    const float* w_f    = (const float*)d_in[6];
    const float* w_i    = (const float*)d_in[7];
    const float* w_c    = (const float*)d_in[8];
    const float* w_o    = (const float*)d_in[9];
    const float* w_r1   = (const float*)d_in[10];
    const float* w_r2   = (const float*)d_in[11];
    const float* w_oil  = (const float*)d_in[12];
    const float* b_oil  = (const float*)d_in[13];
    const float* w_wat  = (const float*)d_in[14];
    const float* b_wat  = (const float*)d_in[15];
    const float* w_gas  = (const float*)d_in[16];
    const float* b_gas  = (const float*)d_in[17];
    float* out = (float*)d_out;

    float *t1, *t2, *gates, *r1, *r2, *mean, *rs;
    double *sum, *sq;
    cudaGetSymbolAddress((void**)&t1,    g_t1);
    cudaGetSymbolAddress((void**)&t2,    g_t2);
    cudaGetSymbolAddress((void**)&gates, g_gates);
    cudaGetSymbolAddress((void**)&r1,    g_r1);
    cudaGetSymbolAddress((void**)&r2,    g_r2);
    cudaGetSymbolAddress((void**)&sum,   g_sum);
    cudaGetSymbolAddress((void**)&sq,    g_sq);
    cudaGetSymbolAddress((void**)&mean,  g_mean);
    cudaGetSymbolAddress((void**)&rs,    g_rs);

    const double invHW = 1.0 / (double)HW;
    const double invS2 = 1.0 / (double)S2;

    dim3 blk(256);
    dim3 g32(32, 32, 1);
    dim3 g33(33, 33, 1);
    dim3 gc2(8, 32, 2);    // conv2: single conv (2 oc-halves)
    dim3 gc8(8, 32, 8);    // conv2: 4 gates x 2 oc-halves

    zero_stats<<<1, 256>>>();

    // e1: x (4ch) -> t1, stats stage 0 (legacy kernel)
    conv_bn<4, 32, 1, 0><<<g32, blk>>>(x, nullptr, w_e1, w_e1, w_e1, w_e1,
                                       t1, 0, nullptr, nullptr, sum + 0, sq + 0);
    finalize_stats<<<1, 32>>>(0, 32, invHW);

    // e2: relu(bn(t1)) -> t2, stats stage 1 (FFMA2 kernel)
    conv2<32, 1><<<gc2, blk>>>(t1, nullptr, w_e2, w_e2, w_e2, w_e2,
                               t2, 0, mean + 0, rs + 0, sum + 32, sq + 32);
    finalize_stats<<<1, 32>>>(1, 32, invHW);

    // gates: concat(prev_h, bn(t2)) -> 4 convs, stats stages 2..5 (FFMA2 kernel)
    conv2<64, 2><<<gc8, blk>>>(t2, prev_h, w_f, w_i, w_c, w_o,
                               gates, (long)CHW, mean + 32, rs + 32, sum + 64, sq + 64);
    finalize_stats<<<4, 32>>>(2, 32, invHW);

    // LSTM pointwise -> next_c, next_h written directly into d_out
    lstm_elem<<<(CHW + 255) / 256, 256>>>(prev_c, out);

    // r1: next_h (raw) -> r1, stats stage 6 (FFMA2 kernel)
    conv2<32, 0><<<gc2, blk>>>(out + CHW, nullptr, w_r1, w_r1, w_r1, w_r1,
                               r1, 0, nullptr, nullptr, sum + 192, sq + 192);
    finalize_stats<<<1, 32>>>(6, 32, invHW);

    // r2: relu(bn(r1)) -> r2 (3ch, 518x518, pad 4), stats stage 7 (legacy)
    conv_bn<32, 3, 4, 1><<<g33, blk>>>(r1, nullptr, w_r2, w_r2, w_r2, w_r2,
                                       r2, 0, mean + 192, rs + 192, sum + 224, sq + 224);
    finalize_stats<<<1, 32>>>(7, 3, invS2);

    // gather + tiny matmul (K=1 scalar) -> res
    gather_k<<<1, 256>>>(holes, w_oil, b_oil, w_wat, b_wat, w_gas, b_gas, out);
}

// round 7
// speedup vs baseline: 1.8247x; 1.3705x over previous
#include <cuda_runtime.h>
#include <math.h>

#define H 512
#define W 512
#define HW (H*W)
#define CH 32
#define CHW (CH*HW)
#define OD2 518            // output dim of pad-4 conv
#define S2 (OD2*OD2)
#define TILE 16
#define ICB 4

// ---------------- scratch (static __device__, no allocation) ----------------
__device__ float g_t1[CHW];          // conv e1 raw output
__device__ float g_t1n[CHW];         // relu(bn(t1))
__device__ float g_t2[CHW];          // conv e2 raw output
__device__ float g_t2n[CHW];         // bn(t2)
__device__ float g_gates[4*CHW];     // f,i,c,o raw conv outputs
__device__ float g_r1[CHW];          // conv r1 raw output
__device__ float g_r2[3*S2];         // conv r2 raw output (518x518)
__device__ double g_sum[8*32];       // per-stage per-channel sum
__device__ double g_sq[8*32];        // per-stage per-channel sum of squares
__device__ float g_mean[8*32];
__device__ float g_rs[8*32];

// ---------------- f32x2 packed-math helpers ----------------
__device__ __forceinline__ unsigned long long dup2(float v) {
    unsigned long long d;
    asm("mov.b64 %0, {%1, %1};" : "=l"(d) : "f"(v));
    return d;
}
__device__ __forceinline__ void fma2(unsigned long long& d,
                                     unsigned long long a, unsigned long long b) {
    asm("fma.rn.f32x2 %0, %1, %2, %0;" : "+l"(d) : "l"(a), "l"(b));
}
__device__ __forceinline__ float2 unpack2(unsigned long long d) {
    float2 f;
    asm("mov.b64 {%0, %1}, %2;" : "=f"(f.x), "=f"(f.y) : "l"(d));
    return f;
}

// ---------------- cp.async helpers ----------------
__device__ __forceinline__ void cp4(unsigned int dst, const float* src, bool pred) {
    int sz = pred ? 4 : 0;
    asm volatile("cp.async.ca.shared.global [%0], [%1], 4, %2;\n"
                 :: "r"(dst), "l"(src), "r"(sz));
}
__device__ __forceinline__ void cp_commit() {
    asm volatile("cp.async.commit_group;");
}
template<int N> __device__ __forceinline__ void cp_wait() {
    asm volatile("cp.async.wait_group %0;" :: "n"(N));
}

// ---------------- small kernels ----------------
__global__ void zero_stats() {
    int i = threadIdx.x;
    g_sum[i] = 0.0; g_sq[i] = 0.0;
}

__global__ void finalize_stats(int stage_base, int nch, double invN) {
    int stage = stage_base + blockIdx.x;
    int t = threadIdx.x;
    if (t < nch) {
        int idx = stage*32 + t;
        double m  = g_sum[idx]*invN;
        double var = g_sq[idx]*invN - m*m;
        g_mean[idx] = (float)m;
        g_rs[idx]   = (float)(1.0 / sqrt(var + 1e-5));
    }
}

// normalize passes (float4): RELU -> relu(bn(x)), else bn(x)
template<int RELU>
__global__ void __launch_bounds__(256)
normalize(const float* __restrict__ in, float* __restrict__ out, int stage)
{
    long i4 = (long)blockIdx.x * 256 + threadIdx.x;      // float4 index
    if (i4 >= CHW/4) return;
    int c = (int)(i4 / (HW/4));
    float m = g_mean[stage*32 + c], rs = g_rs[stage*32 + c];
    float4 v = ((const float4*)in)[i4];
    v.x = (v.x - m)*rs; v.y = (v.y - m)*rs; v.z = (v.z - m)*rs; v.w = (v.w - m)*rs;
    if (RELU) {
        v.x = v.x > 0.f ? v.x : 0.f; v.y = v.y > 0.f ? v.y : 0.f;
        v.z = v.z > 0.f ? v.z : 0.f; v.w = v.w > 0.f ? v.w : 0.f;
    }
    ((float4*)out)[i4] = v;
}

// ---------------- FFMA2 conv3x3, cp.async double-buffered ----------------
// Tile: 64 wide x 16 tall; thread = 4 px (x) x 16 oc (8 oc-pairs).
// blockIdx.z = gate*2 + oc_half. Raw inputs only (transform done upstream).
// SPLIT=1: channel c<32 from in2 (prev_h), c>=32 from in (t2n).
template<int CIN, int SPLIT>
__global__ void __launch_bounds__(256, 2)
conv2(const float* __restrict__ in, const float* __restrict__ in2,
      const float* __restrict__ w0_, const float* __restrict__ w1_,
      const float* __restrict__ w2_, const float* __restrict__ w3_,
      float* __restrict__ out, long outStrideZ,
      double* __restrict__ o_sum, double* __restrict__ o_sq)
{
    constexpr int NCH = CIN / ICB;
    constexpr int NIN = ICB*18*66;          // 4752 input elements per chunk
    constexpr int NWT = ICB*9*16;           // 576 weight elements per chunk
    constexpr int NTOT = NIN + NWT;         // 5328

    const int z    = blockIdx.z;
    const int gate = z >> 1;
    const int ocbase = (z & 1) * 16;
    const float* wt = (gate == 0) ? w0_ : (gate == 1) ? w1_ : (gate == 2) ? w2_ : w3_;
    out   += (long)gate * outStrideZ;
    o_sum += gate*32 + ocbase;
    o_sq  += gate*32 + ocbase;

    __shared__ float s_in[2][ICB][18][68];
    __shared__ float s_w[2][ICB][9][16];
    __shared__ float s_red[8][16][2];

    const int tid = threadIdx.x;
    const int tx = tid & 15, ty = tid >> 4;
    const int x0 = blockIdx.x*64 + tx*4;
    const int oy = blockIdx.y*16 + ty;
    const int gx0 = blockIdx.x*64 - 1;
    const int gy0 = blockIdx.y*16 - 1;

    unsigned long long acc[4][8];
#pragma unroll
    for (int p = 0; p < 4; p++)
#pragma unroll
        for (int q = 0; q < 8; q++) acc[p][q] = 0ULL;

    // issue loads for chunk `ch` into buffer `b`
    auto issue = [&](int ch, int b) {
        int ic0 = ch * ICB;
        for (int e = tid; e < NTOT; e += 256) {
            if (e < NIN) {
                int ic = e / (18*66);
                int r  = e - ic*(18*66);
                int ly = r / 66, lx = r - ly*66;
                int gy = gy0 + ly, gx = gx0 + lx;
                bool ok = (unsigned)gy < (unsigned)H && (unsigned)gx < (unsigned)W;
                int c = ic0 + ic;
                const float* src;
                if (SPLIT && c < 32)
                    src = ok ? &in2[(long)c*HW + gy*W + gx] : in2;
                else {
                    int cc = SPLIT ? c - 32 : c;
                    src = ok ? &in[(long)cc*HW + gy*W + gx] : in;
                }
                cp4((unsigned int)__cvta_generic_to_shared(&s_in[b][ic][ly][lx]), src, ok);
            } else {
                int r  = e - NIN;
                int ic = r / 144;
                int r2 = r - ic*144;
                int k  = r2 >> 4, oco = r2 & 15;
                const float* src = &wt[((long)(ocbase + oco)*CIN + ic0 + ic)*9 + k];
                cp4((unsigned int)__cvta_generic_to_shared(&s_w[b][ic][k][oco]), src, true);
            }
        }
        cp_commit();
    };

    issue(0, 0);

    for (int n = 0; n < NCH; n++) {
        const int b = n & 1;
        if (n + 1 < NCH) {
            issue(n + 1, (n + 1) & 1);
            cp_wait<1>();
        } else {
            cp_wait<0>();
        }
        __syncthreads();

#pragma unroll
        for (int i = 0; i < ICB; i++) {
#pragma unroll
            for (int r = 0; r < 3; r++) {
                float4 va = *(const float4*)&s_in[b][i][ty + r][tx*4];
                float2 vb = *(const float2*)&s_in[b][i][ty + r][tx*4 + 4];
                unsigned long long d[6] = { dup2(va.x), dup2(va.y), dup2(va.z),
                                            dup2(va.w), dup2(vb.x), dup2(vb.y) };
#pragma unroll
                for (int c = 0; c < 3; c++) {
                    const ulonglong2* wr = (const ulonglong2*)&s_w[b][i][r*3 + c][0];
                    ulonglong2 wa = wr[0], wb2 = wr[1], wc = wr[2], wd = wr[3];
                    unsigned long long wv[8] = { wa.x, wa.y, wb2.x, wb2.y,
                                                 wc.x, wc.y, wd.x, wd.y };
#pragma unroll
                    for (int p = 0; p < 4; p++) {
#pragma unroll
                        for (int q = 0; q < 8; q++)
                            fma2(acc[p][q], d[c + p], wv[q]);
                    }
                }
            }
        }
        __syncthreads();
    }

    // ---- output (float4 stores) + BN stats ----
    const int lane = tid & 31, wid = tid >> 5;
    const long obase = (long)oy*W + x0;
#pragma unroll
    for (int q = 0; q < 8; q++) {
        float2 v0 = unpack2(acc[0][q]), v1 = unpack2(acc[1][q]);
        float2 v2 = unpack2(acc[2][q]), v3 = unpack2(acc[3][q]);
        float4 lo = make_float4(v0.x, v1.x, v2.x, v3.x);
        float4 hi = make_float4(v0.y, v1.y, v2.y, v3.y);
        *(float4*)(out + (long)(ocbase + 2*q    )*HW + obase) = lo;
        *(float4*)(out + (long)(ocbase + 2*q + 1)*HW + obase) = hi;

        float sl = lo.x + lo.y + lo.z + lo.w;
        float ql = lo.x*lo.x + lo.y*lo.y + lo.z*lo.z + lo.w*lo.w;
        float sh = hi.x + hi.y + hi.z + hi.w;
        float qh = hi.x*hi.x + hi.y*hi.y + hi.z*hi.z + hi.w*hi.w;
#pragma unroll
        for (int o2 = 16; o2 > 0; o2 >>= 1) {
            sl += __shfl_xor_sync(0xffffffffu, sl, o2);
            ql += __shfl_xor_sync(0xffffffffu, ql, o2);
            sh += __shfl_xor_sync(0xffffffffu, sh, o2);
            qh += __shfl_xor_sync(0xffffffffu, qh, o2);
        }
        if (lane == 0) {
            s_red[wid][2*q    ][0] = sl; s_red[wid][2*q    ][1] = ql;
            s_red[wid][2*q + 1][0] = sh; s_red[wid][2*q + 1][1] = qh;
        }
    }
    __syncthreads();
    if (tid < 16) {
        double s = 0.0, qq = 0.0;
#pragma unroll
        for (int wdx = 0; wdx < 8; wdx++) {
            s  += (double)s_red[wdx][tid][0];
            qq += (double)s_red[wdx][tid][1];
        }
        atomicAdd(&o_sum[tid], s);
        atomicAdd(&o_sq[tid], qq);
    }
}

// ---------------- legacy conv (e1 (CIN=4) and r2 (COUT=3, 518-wide)) ----------
template<int CIN, int COUT, int PAD, int MODE>
__global__ void __launch_bounds__(256)
conv_bn(const float* __restrict__ in, const float* __restrict__ in2,
        const float* __restrict__ w0_, const float* __restrict__ w1_,
        const float* __restrict__ w2_, const float* __restrict__ w3_,
        float* __restrict__ out, long outStrideZ,
        const float* __restrict__ bn_mean, const float* __restrict__ bn_rs,
        double* __restrict__ o_sum, double* __restrict__ o_sq)
{
    constexpr int OWID = W + 2*PAD - 2;
    constexpr int OHEI = H + 2*PAD - 2;

    const int z = blockIdx.z;
    const float* wt = (z == 0) ? w0_ : (z == 1) ? w1_ : (z == 2) ? w2_ : w3_;
    out   += (long)z * outStrideZ;
    o_sum += z * COUT;
    o_sq  += z * COUT;

    __shared__ float s_in[ICB][18][18];
    __shared__ float s_w[ICB][COUT][12];
    __shared__ float s_red[8][COUT][2];

    const int tid = threadIdx.x;
    const int px = tid & 15, py = tid >> 4;
    const int ox = blockIdx.x*TILE + px;
    const int oy = blockIdx.y*TILE + py;
    const bool valid = (ox < OWID) && (oy < OHEI);

    float acc[COUT];
#pragma unroll
    for (int i = 0; i < COUT; i++) acc[i] = 0.f;

    const int gx0 = blockIdx.x*TILE - PAD;
    const int gy0 = blockIdx.y*TILE - PAD;

    for (int ic0 = 0; ic0 < CIN; ic0 += ICB) {
        __syncthreads();
        for (int e = tid; e < ICB*18*18; e += 256) {
            int ic = e / 324; int r = e - ic*324;
            int ly = r / 18, lx = r - ly*18;
            int gy = gy0 + ly, gx = gx0 + lx;
            float v = 0.f;
            if ((unsigned)gy < (unsigned)H && (unsigned)gx < (unsigned)W) {
                int c = ic0 + ic;
                if (MODE == 0) {
                    v = in[(long)c*HW + gy*W + gx];
                } else if (MODE == 1) {
                    float t = in[(long)c*HW + gy*W + gx];
                    t = (t - bn_mean[c]) * bn_rs[c];
                    v = t > 0.f ? t : 0.f;
                } else {
                    if (c < 32) {
                        v = in2[(long)c*HW + gy*W + gx];
                    } else {
                        float t = in[(long)(c-32)*HW + gy*W + gx];
                        v = (t - bn_mean[c-32]) * bn_rs[c-32];
                    }
                }
            }
            s_in[ic][ly][lx] = v;
        }
        for (int e = tid; e < ICB*COUT*12; e += 256) {
            int ic = e / (COUT*12); int r = e - ic*(COUT*12);
            int oc = r / 12, k = r - oc*12;
            s_w[ic][oc][k] = (k < 9) ? wt[((long)oc*CIN + ic0 + ic)*9 + k] : 0.f;
        }
        __syncthreads();

#pragma unroll
        for (int i = 0; i < ICB; i++) {
            float i00 = s_in[i][py+0][px+0], i01 = s_in[i][py+0][px+1], i02 = s_in[i][py+0][px+2];
            float i10 = s_in[i][py+1][px+0], i11 = s_in[i][py+1][px+1], i12 = s_in[i][py+1][px+2];
            float i20 = s_in[i][py+2][px+0], i21 = s_in[i][py+2][px+1], i22 = s_in[i][py+2][px+2];
#pragma unroll
            for (int oc = 0; oc < COUT; oc++) {
                const float4* wp = (const float4*)&s_w[i][oc][0];
                float4 a = wp[0], b = wp[1], c4 = wp[2];
                acc[oc] += i00*a.x + i01*a.y + i02*a.z
                         + i10*a.w + i11*b.x + i12*b.y
                         + i20*b.z + i21*b.w + i22*c4.x;
            }
        }
    }

    const int lane = tid & 31, wid = tid >> 5;
#pragma unroll
    for (int oc = 0; oc < COUT; oc++) {
        float v = valid ? acc[oc] : 0.f;
        if (valid) out[(long)oc*OHEI*OWID + (long)oy*OWID + ox] = v;
        float s = v, q = v*v;
#pragma unroll
        for (int o2 = 16; o2 > 0; o2 >>= 1) {
            s += __shfl_xor_sync(0xffffffffu, s, o2);
            q += __shfl_xor_sync(0xffffffffu, q, o2);
        }
        if (lane == 0) { s_red[wid][oc][0] = s; s_red[wid][oc][1] = q; }
    }
    __syncthreads();
    if (tid < COUT) {
        double s = 0.0, q = 0.0;
#pragma unroll
        for (int wdx = 0; wdx < 8; wdx++) { s += (double)s_red[wdx][tid][0]; q += (double)s_red[wdx][tid][1]; }
        atomicAdd(&o_sum[tid], s);
        atomicAdd(&o_sq[tid], q);
    }
}

// ---------------- LSTM elementwise ----------------
__device__ __forceinline__ float sigmoidf(float x) { return 1.f / (1.f + expf(-x)); }

__global__ void lstm_elem(const float* __restrict__ prev_c, float* __restrict__ out)
{
    long i = (long)blockIdx.x * blockDim.x + threadIdx.x;
    if (i >= CHW) return;
    int c = (int)(i / HW);
    float f  = sigmoidf((g_gates[i]          - g_mean[64  + c]) * g_rs[64  + c]);
    float it = sigmoidf((g_gates[CHW + i]    - g_mean[96  + c]) * g_rs[96  + c]);
    float ct = tanhf(   (g_gates[2L*CHW + i] - g_mean[128 + c]) * g_rs[128 + c]);
    float ot = sigmoidf((g_gates[3L*CHW + i] - g_mean[160 + c]) * g_rs[160 + c]);
    float nc = prev_c[i] * f + it * ct;
    float nh = tanhf(nc) * ot;
    out[i] = nc;
    out[CHW + i] = nh;
}

// ---------------- gather (K=1 -> single pixel at (hx+3, hy+3)) ----------------
__global__ void gather_k(const int* __restrict__ coords,
                         const float* __restrict__ w_oil, const float* __restrict__ b_oil,
                         const float* __restrict__ w_wat, const float* __restrict__ b_wat,
                         const float* __restrict__ w_gas, const float* __restrict__ b_gas,
                         float* __restrict__ out)
{
    int i = threadIdx.x;
    if (i >= 256) return;
    int hx = coords[2*i], hy = coords[2*i+1];
    int row = hx + 3, col = hy + 3;
    float wv[3] = { w_oil[0], w_wat[0], w_gas[0] };
    float bv[3] = { b_oil[0], b_wat[0], b_gas[0] };
#pragma unroll
    for (int ch = 0; ch < 3; ch++) {
        float v = (g_r2[(long)ch*S2 + (long)row*OD2 + col] - g_mean[224 + ch]) * g_rs[224 + ch];
        out[2L*CHW + (long)i*3 + ch] = v * wv[ch] + bv[ch];
    }
}

// ---------------- launch ----------------
extern "C" void kernel_launch(void* const* d_in, const int* in_sizes, int n_in,
                              void* d_out, int out_size)
{
    const float* x      = (const float*)d_in[0];
    const float* prev_c = (const float*)d_in[1];
    const float* prev_h = (const float*)d_in[2];
    const int*   holes  = (const int*)  d_in[3];
    const float* w_e1   = (const float*)d_in[4];
    const float* w_e2   = (const float*)d_in[5];
    const float* w_f    = (const float*)d_in[6];
    const float* w_i    = (const float*)d_in[7];
    const float* w_c    = (const float*)d_in[8];
    const float* w_o    = (const float*)d_in[9];
    const float* w_r1   = (const float*)d_in[10];
    const float* w_r2   = (const float*)d_in[11];
    const float* w_oil  = (const float*)d_in[12];
    const float* b_oil  = (const float*)d_in[13];
    const float* w_wat  = (const float*)d_in[14];
    const float* b_wat  = (const float*)d_in[15];
    const float* w_gas  = (const float*)d_in[16];
    const float* b_gas  = (const float*)d_in[17];
    float* out = (float*)d_out;

    float *t1, *t1n, *t2, *t2n, *gates, *r1, *r2, *mean, *rs;
    double *sum, *sq;
    cudaGetSymbolAddress((void**)&t1,    g_t1);
    cudaGetSymbolAddress((void**)&t1n,   g_t1n);
    cudaGetSymbolAddress((void**)&t2,    g_t2);
    cudaGetSymbolAddress((void**)&t2n,   g_t2n);
    cudaGetSymbolAddress((void**)&gates, g_gates);
    cudaGetSymbolAddress((void**)&r1,    g_r1);
    cudaGetSymbolAddress((void**)&r2,    g_r2);
    cudaGetSymbolAddress((void**)&sum,   g_sum);
    cudaGetSymbolAddress((void**)&sq,    g_sq);
    cudaGetSymbolAddress((void**)&mean,  g_mean);
    cudaGetSymbolAddress((void**)&rs,    g_rs);

    const double invHW = 1.0 / (double)HW;
    const double invS2 = 1.0 / (double)S2;

    dim3 blk(256);
    dim3 g32(32, 32, 1);
    dim3 g33(33, 33, 1);
    dim3 gc2(8, 32, 2);    // conv2: single conv (2 oc-halves)
    dim3 gc8(8, 32, 8);    // conv2: 4 gates x 2 oc-halves
    const int NB4 = (CHW/4 + 255) / 256;

    zero_stats<<<1, 256>>>();

    // e1: x (4ch) -> t1, stats stage 0 (legacy kernel)
    conv_bn<4, 32, 1, 0><<<g32, blk>>>(x, nullptr, w_e1, w_e1, w_e1, w_e1,
                                       t1, 0, nullptr, nullptr, sum + 0, sq + 0);
    finalize_stats<<<1, 32>>>(0, 32, invHW);

    // t1n = relu(bn(t1))
    normalize<1><<<NB4, 256>>>(t1, t1n, 0);

    // e2: conv(t1n) -> t2, stats stage 1 (pipelined FFMA2 kernel)
    conv2<32, 0><<<gc2, blk>>>(t1n, nullptr, w_e2, w_e2, w_e2, w_e2,
                               t2, 0, sum + 32, sq + 32);
    finalize_stats<<<1, 32>>>(1, 32, invHW);

    // t2n = bn(t2)
    normalize<0><<<NB4, 256>>>(t2, t2n, 1);

    // gates: concat(prev_h, t2n) via split pointers, stats stages 2..5
    conv2<64, 1><<<gc8, blk>>>(t2n, prev_h, w_f, w_i, w_c, w_o,
                               gates, (long)CHW, sum + 64, sq + 64);
    finalize_stats<<<4, 32>>>(2, 32, invHW);

    // LSTM pointwise -> next_c, next_h written directly into d_out
    lstm_elem<<<(CHW + 255) / 256, 256>>>(prev_c, out);

    // r1: conv(next_h raw) -> r1, stats stage 6
    conv2<32, 0><<<gc2, blk>>>(out + CHW, nullptr, w_r1, w_r1, w_r1, w_r1,
                               r1, 0, sum + 192, sq + 192);
    finalize_stats<<<1, 32>>>(6, 32, invHW);

    // r2: relu(bn(r1)) -> r2 (3ch, 518x518, pad 4), stats stage 7 (legacy)
    conv_bn<32, 3, 4, 1><<<g33, blk>>>(r1, nullptr, w_r2, w_r2, w_r2, w_r2,
                                       r2, 0, mean + 192, rs + 192, sum + 224, sq + 224);
    finalize_stats<<<1, 32>>>(7, 3, invS2);

    // gather + tiny matmul (K=1 scalar) -> res
    gather_k<<<1, 256>>>(holes, w_oil, b_oil, w_wat, b_wat, w_gas, b_gas, out);
}